// round 8
// baseline (speedup 1.0000x reference)
#include <cuda_runtime.h>
#include <cuda_bf16.h>
#include <math.h>

#define N_OSC 32
#define CONVC 1000.0f
#define NBLK 148
#define TPB   1024   // 32 warps

// -------- scratch (no allocations allowed) --------
__device__ float g_h1[4096];
__device__ float g_h2[4096];
__device__ float g_params[2112];
__device__ float g_cpg[64];
__device__ float g_h3[2048];
__device__ unsigned g_count[8];   // zero-init; each barrier resets itself
__device__ unsigned g_flag[8];    // monotonically increasing epochs

// -------- grid-wide barrier (all NBLK blocks co-resident) --------
__device__ __forceinline__ void grid_barrier(int id, unsigned base) {
    __syncthreads();                        // block's work done, writes issued
    if (threadIdx.x == 0) {
        __threadfence();                    // make writes visible at L2
        if (atomicAdd(&g_count[id], 1u) == NBLK - 1) {
            g_count[id] = 0;                // reset for next launch
            __threadfence();
            atomicAdd(&g_flag[id], 1u);     // release
        } else {
            volatile unsigned* f = &g_flag[id];
            while (*f == base) { }          // acquire spin (bypasses L1)
        }
        __threadfence();
    }
    __syncthreads();                        // release whole block
}

__device__ __forceinline__ float warp_sum(float s) {
    #pragma unroll
    for (int o = 16; o; o >>= 1) s += __shfl_xor_sync(0xFFFFFFFFu, s, o);
    return s;
}

// warp-per-row float4 matvec; rows striped as r = b + NBLK*w
template <bool RELU, int ROWS, int C4>
__device__ __forceinline__ void layerv(const float* __restrict__ W,
                                       const float* __restrict__ bias,
                                       const float* __restrict__ xv,
                                       float* __restrict__ y,
                                       int b, int w, int lane) {
    int r = b + NBLK * w;
    if (r < ROWS) {
        const float4* __restrict__ w4 = reinterpret_cast<const float4*>(W) + (size_t)r * C4;
        const float4* __restrict__ x4 = reinterpret_cast<const float4*>(xv);
        float s = 0.f, s2 = 0.f;
        #pragma unroll 8
        for (int k = lane; k < C4; k += 32) {
            float4 a = w4[k];
            float4 v = x4[k];
            s  += a.x * v.x + a.y * v.y;
            s2 += a.z * v.z + a.w * v.w;
        }
        s = warp_sum(s + s2);
        if (lane == 0) {
            s += bias[r];
            if (RELU) s = fmaxf(s, 0.f);
            y[r] = s;
        }
    }
}

// ============ THE WHOLE NETWORK, one persistent kernel ============
__global__ __launch_bounds__(TPB, 1) void cpg_net_kernel(
        const float* __restrict__ state, const float* __restrict__ x,
        const float* __restrict__ ts,
        const float* __restrict__ iW0, const float* __restrict__ ib0,
        const float* __restrict__ iW1, const float* __restrict__ ib1,
        const float* __restrict__ iW2, const float* __restrict__ ib2,
        const float* __restrict__ oW0, const float* __restrict__ ob0,
        const float* __restrict__ oW1, const float* __restrict__ ob1,
        const float* __restrict__ oW2, const float* __restrict__ ob2,
        float* __restrict__ out /* [new_state(96), out(1024)] */) {
    __shared__ unsigned s_base[8];
    __shared__ float s_cw[N_OSC * 33];
    __shared__ float s_pb[N_OSC * 33];
    __shared__ float s_ph[N_OSC];

    int b    = blockIdx.x;
    int w    = threadIdx.x >> 5;
    int lane = threadIdx.x & 31;

    // epoch bases: stable at entry (a flag can only advance after ALL blocks
    // have passed this point; previous launch fully completed)
    if (threadIdx.x < 8) s_base[threadIdx.x] = g_flag[threadIdx.x];
    __syncthreads();

    // ---- L1: h1 = relu(iW0 @ [x, ts] + ib0)   [4096 x 2049], scalar ----
    {
        int r = b + NBLK * w;
        if (r < 4096) {
            const float* __restrict__ wr = iW0 + (size_t)r * 2049;
            float s = 0.f;
            #pragma unroll 8
            for (int c = lane; c < 2048; c += 32) s += wr[c] * x[c];
            if (lane == 0) s += wr[2048] * ts[0];
            s = warp_sum(s);
            if (lane == 0) g_h1[r] = fmaxf(s + ib0[r], 0.f);
        }
    }
    grid_barrier(0, s_base[0]);

    // ---- L2: h2 = relu(iW1 @ h1 + ib1)   [4096 x 4096] ----
    layerv<true, 4096, 1024>(iW1, ib1, g_h1, g_h2, b, w, lane);
    grid_barrier(1, s_base[1]);

    // ---- L3: params = iW2 @ h2 + ib2     [2112 x 4096] ----
    layerv<false, 2112, 1024>(iW2, ib2, g_h2, g_params, b, w, lane);
    grid_barrier(2, s_base[2]);

    // ---- ODE: RK4 3/8, single warp on block 0 ----
    // Replicates reference slicing exactly: phase_dots go into the a_dot
    // slot; post-step "ph" is read from that slot for cpg_out.
    if (b == 0 && threadIdx.x < 32) {
        int i = lane;
        // coupling matrices into shared, stride-33 (conflict-free)
        for (int idx = lane; idx < N_OSC * N_OSC; idx += 32) {
            int ii = idx >> 5, jj = idx & 31;
            s_cw[ii * 33 + jj] = g_params[2 * N_OSC + idx];
            s_pb[ii * 33 + jj] = g_params[2 * N_OSC + N_OSC * N_OSC + idx];
        }
        __syncwarp();

        float h   = ts[0];
        float ya  = state[i];
        float yad = state[N_OSC + i];
        float yph = state[2 * N_OSC + i];
        float ia  = g_params[i];
        float ifr = g_params[N_OSC + i];

        float k1a, k1ad, k1ph, k2a, k2ad, k2ph, k3a, k3ad, k3ph, k4a, k4ad, k4ph;

        auto stage = [&](float ea, float ead, float eph,
                         float& ka, float& kad, float& kph) {
            s_ph[i] = eph;
            __syncwarp();
            float t = 0.f;
            #pragma unroll
            for (int j = 0; j < N_OSC; ++j)
                t += s_cw[i * 33 + j] * __sinf(s_ph[j] - eph - s_pb[i * 33 + j]);
            __syncwarp();
            kad = ifr + ea * t;                                // phase_dots
            ka  = ead;                                         // a_dot
            kph = CONVC * (CONVC * 0.25f * (ia - ea) - ead);   // a_dd
        };

        stage(ya, yad, yph, k1a, k1ad, k1ph);
        stage(ya + h * k1a / 3.0f, yad + h * k1ad / 3.0f, yph + h * k1ph / 3.0f,
              k2a, k2ad, k2ph);
        stage(ya + h * (k2a - k1a / 3.0f),
              yad + h * (k2ad - k1ad / 3.0f),
              yph + h * (k2ph - k1ph / 3.0f),
              k3a, k3ad, k3ph);
        stage(ya + h * (k1a - k2a + k3a),
              yad + h * (k1ad - k2ad + k3ad),
              yph + h * (k1ph - k2ph + k3ph),
              k4a, k4ad, k4ph);

        float yna  = ya  + h * 0.125f * (k1a  + 3.0f * (k2a  + k3a)  + k4a);
        float ynad = yad + h * 0.125f * (k1ad + 3.0f * (k2ad + k3ad) + k4ad);
        float ynph = yph + h * 0.125f * (k1ph + 3.0f * (k2ph + k3ph) + k4ph);

        out[i]             = yna;
        out[N_OSC + i]     = ynad;
        out[2 * N_OSC + i] = ynph;

        // reference reads ns[:n] as a and ns[n:2n] (the a_dot slot) as ph
        g_cpg[i]         = yna * __cosf(ynad);
        g_cpg[N_OSC + i] = yna * __sinf(ynad);
    }
    grid_barrier(3, s_base[3]);

    // ---- L4: h3 = relu(oW0 @ cpg + ob0)  [2048 x 64] ----
    {
        int r = b + NBLK * w;
        if (r < 2048) {
            float2 ww = reinterpret_cast<const float2*>(oW0 + (size_t)r * 64)[lane];
            float2 cc = reinterpret_cast<const float2*>(g_cpg)[lane];
            float s = warp_sum(ww.x * cc.x + ww.y * cc.y);
            if (lane == 0) g_h3[r] = fmaxf(s + ob0[r], 0.f);
        }
    }
    grid_barrier(4, s_base[4]);

    // ---- L5: h4 = relu(oW1 @ h3 + ob1)   [2048 x 2048] ----
    layerv<true, 2048, 512>(oW1, ob1, g_h3, g_h1 /*reuse as h4*/, b, w, lane);
    grid_barrier(5, s_base[5]);

    // ---- L6: out = oW2 @ h4 + ob2        [1024 x 2048] -> out[96:1120] ----
    layerv<false, 1024, 512>(oW2, ob2, g_h1, out + 96, b, w, lane);
}

extern "C" void kernel_launch(void* const* d_in, const int* in_sizes, int n_in,
                              void* d_out, int out_size) {
    const float* state = (const float*)d_in[0];
    const float* x     = (const float*)d_in[1];
    const float* ts    = (const float*)d_in[2];
    const float* iW0   = (const float*)d_in[3];
    const float* ib0   = (const float*)d_in[4];
    const float* iW1   = (const float*)d_in[5];
    const float* ib1   = (const float*)d_in[6];
    const float* iW2   = (const float*)d_in[7];
    const float* ib2   = (const float*)d_in[8];
    const float* oW0   = (const float*)d_in[9];
    const float* ob0   = (const float*)d_in[10];
    const float* oW1   = (const float*)d_in[11];
    const float* ob1   = (const float*)d_in[12];
    const float* oW2   = (const float*)d_in[13];
    const float* ob2   = (const float*)d_in[14];
    float* out = (float*)d_out;   // [new_state(96), out(1024)]

    cpg_net_kernel<<<NBLK, TPB>>>(state, x, ts,
                                  iW0, ib0, iW1, ib1, iW2, ib2,
                                  oW0, ob0, oW1, ob1, oW2, ob2, out);
}